// round 2
// baseline (speedup 1.0000x reference)
#include <cuda_runtime.h>
#include <math_constants.h>

#define BB   4
#define NP   2048
#define KNN  64
#define EPS  0.005f
#define LOG_MU (-7.6246190f)   /* -log(2048) */

/* ------------ scratch (no allocations allowed) ------------ */
__device__ float g_lu[BB*NP];
__device__ float g_lv[BB*NP];
__device__ float g_sin[BB*NP];
__device__ float g_spr[BB*NP];
__device__ int   g_assign[BB*NP];
__device__ float g_avg[BB*NP];

/* TF32 rounding (cuBLAS/CUTLASS conversion path: round-nearest-ties-away) */
__device__ __forceinline__ float tf32r(float x)
{
    float r;
    asm("cvt.rna.tf32.f32 %0, %1;" : "=f"(r) : "f"(x));
    return r;
}

/* ------------ threefry2x32, bit-exact vs JAX ------------ */
__device__ __forceinline__ void threefry2x32(unsigned k0, unsigned k1,
                                             unsigned &x0, unsigned &x1)
{
    unsigned ks2 = k0 ^ k1 ^ 0x1BD11BDAu;
    x0 += k0; x1 += k1;
#define TFR(r) { x0 += x1; x1 = (x1 << (r)) | (x1 >> (32 - (r))); x1 ^= x0; }
    TFR(13) TFR(15) TFR(26) TFR(6)
    x0 += k1;  x1 += ks2 + 1u;
    TFR(17) TFR(29) TFR(16) TFR(24)
    x0 += ks2; x1 += k0 + 2u;
    TFR(13) TFR(15) TFR(26) TFR(6)
    x0 += k0;  x1 += k1 + 3u;
    TFR(17) TFR(29) TFR(16) TFR(24)
    x0 += k1;  x1 += ks2 + 4u;
    TFR(13) TFR(15) TFR(26) TFR(6)
    x0 += ks2; x1 += k0 + 5u;
#undef TFR
}

/* ------------ init: squared norms (full fp32) + zero duals ------------ */
__global__ void init_kernel(const float* __restrict__ preds,
                            const float* __restrict__ inputs)
{
    int i = blockIdx.x * blockDim.x + threadIdx.x;
    if (i < BB*NP) {
        float x = inputs[3*i], y = inputs[3*i+1], z = inputs[3*i+2];
        g_sin[i] = fmaf(z, z, fmaf(y, y, x*x));
        x = preds[3*i]; y = preds[3*i+1]; z = preds[3*i+2];
        g_spr[i] = fmaf(z, z, fmaf(y, y, x*x));
        g_lu[i] = 0.f;
        g_lv[i] = 0.f;
    }
}

/* pairwise logK entry, mimicking XLA:
   dot  : TF32-rounded operands, fp32 fma-chain accumulate (exact products)
   d2   : (sa + sb) - 2*dot, elementwise fp32, explicit rounding (no fma fold)
   logK : -(d2 / eps) (true division), then + dual                           */
__device__ __forceinline__ float logk_entry(float ax, float ay, float az, float sa,
                                            float4 p /* tf32 xyz, w = norm */)
{
    float dot = fmaf(az, p.z, fmaf(ay, p.y, ax * p.x));
    float d2  = fmaxf(__fadd_rn(__fadd_rn(sa, p.w), -2.0f * dot), 0.f);
    return -(d2 / EPS);
}

/* ------------ one Sinkhorn half-step ------------
   DIR==0: update lu (rows = inputs, inner = preds, dual-in = lv)
   DIR==1: update lv (rows = preds, inner = inputs, dual-in = lu)  */
template<int DIR>
__global__ void __launch_bounds__(256) sinkhorn_half(
    const float* __restrict__ rowPts,
    const float* __restrict__ innerPts)
{
    __shared__ float4 shp[NP];
    __shared__ float  shl[NP];

    const float* rowS   = (DIR == 0) ? g_sin : g_spr;
    const float* innerS = (DIR == 0) ? g_spr : g_sin;
    const float* dualIn = (DIR == 0) ? g_lv  : g_lu;
    float*       dualOut= (DIR == 0) ? g_lu  : g_lv;

    int b = blockIdx.y;
    const float* ip = innerPts + b*NP*3;
    for (int i = threadIdx.x; i < NP; i += 256) {
        shp[i] = make_float4(tf32r(ip[3*i]), tf32r(ip[3*i+1]), tf32r(ip[3*i+2]),
                             innerS[b*NP + i]);
        shl[i] = dualIn[b*NP + i];
    }
    __syncthreads();

    int warp = threadIdx.x >> 5, lane = threadIdx.x & 31;
    int row0 = blockIdx.x * 16 + warp * 2;
    const float* rp = rowPts + (b*NP + row0)*3;
    float a0x = tf32r(rp[0]), a0y = tf32r(rp[1]), a0z = tf32r(rp[2]);
    float a1x = tf32r(rp[3]), a1y = tf32r(rp[4]), a1z = tf32r(rp[5]);
    float sa0 = rowS[b*NP + row0], sa1 = rowS[b*NP + row0 + 1];

    float mx0 = -CUDART_INF_F, s0 = 0.f;
    float mx1 = -CUDART_INF_F, s1 = 0.f;

    for (int m = lane; m < NP; m += 32) {
        float4 p  = shp[m];
        float  lv = shl[m];
        float e0 = __fadd_rn(logk_entry(a0x, a0y, a0z, sa0, p), lv);
        float e1 = __fadd_rn(logk_entry(a1x, a1y, a1z, sa1, p), lv);
        if (e0 > mx0) { s0 = fmaf(s0, expf(mx0 - e0), 1.f); mx0 = e0; }
        else            s0 += expf(e0 - mx0);
        if (e1 > mx1) { s1 = fmaf(s1, expf(mx1 - e1), 1.f); mx1 = e1; }
        else            s1 += expf(e1 - mx1);
    }

#pragma unroll
    for (int off = 16; off; off >>= 1) {
        float om = __shfl_xor_sync(0xffffffffu, mx0, off);
        float os = __shfl_xor_sync(0xffffffffu, s0,  off);
        float nm = fmaxf(mx0, om);
        s0 = s0 * expf(mx0 - nm) + os * expf(om - nm);
        mx0 = nm;
        om = __shfl_xor_sync(0xffffffffu, mx1, off);
        os = __shfl_xor_sync(0xffffffffu, s1,  off);
        nm = fmaxf(mx1, om);
        s1 = s1 * expf(mx1 - nm) + os * expf(om - nm);
        mx1 = nm;
    }
    if (lane == 0) {
        float r0 = __fadd_rn(logf(s0), mx0);
        float r1 = __fadd_rn(logf(s1), mx1);
        dualOut[b*NP + row0]     = __fadd_rn(LOG_MU, -r0);
        dualOut[b*NP + row0 + 1] = __fadd_rn(LOG_MU, -r1);
    }
}

/* ------------ argmax over m of logK[n,m] + lv[m]  ------------ */
__global__ void __launch_bounds__(256) assign_kernel(
    const float* __restrict__ inputs,
    const float* __restrict__ preds)
{
    __shared__ float4 shp[NP];
    __shared__ float  shl[NP];

    int b = blockIdx.y;
    const float* ip = preds + b*NP*3;
    for (int i = threadIdx.x; i < NP; i += 256) {
        shp[i] = make_float4(tf32r(ip[3*i]), tf32r(ip[3*i+1]), tf32r(ip[3*i+2]),
                             g_spr[b*NP + i]);
        shl[i] = g_lv[b*NP + i];
    }
    __syncthreads();

    int warp = threadIdx.x >> 5, lane = threadIdx.x & 31;
    int row0 = blockIdx.x * 16 + warp * 2;
    const float* rp = inputs + (b*NP + row0)*3;
    float a0x = tf32r(rp[0]), a0y = tf32r(rp[1]), a0z = tf32r(rp[2]);
    float a1x = tf32r(rp[3]), a1y = tf32r(rp[4]), a1z = tf32r(rp[5]);
    float sa0 = g_sin[b*NP + row0], sa1 = g_sin[b*NP + row0 + 1];

    float best0 = -CUDART_INF_F, best1 = -CUDART_INF_F;
    int   bi0 = 0, bi1 = 0;

    for (int m = lane; m < NP; m += 32) {
        float4 p  = shp[m];
        float  lv = shl[m];
        float v0 = __fadd_rn(logk_entry(a0x, a0y, a0z, sa0, p), lv);
        float v1 = __fadd_rn(logk_entry(a1x, a1y, a1z, sa1, p), lv);
        if (v0 > best0) { best0 = v0; bi0 = m; }
        if (v1 > best1) { best1 = v1; bi1 = m; }
    }
#pragma unroll
    for (int off = 16; off; off >>= 1) {
        float ov = __shfl_xor_sync(0xffffffffu, best0, off);
        int   oi = __shfl_xor_sync(0xffffffffu, bi0,   off);
        if (ov > best0 || (ov == best0 && oi < bi0)) { best0 = ov; bi0 = oi; }
        ov = __shfl_xor_sync(0xffffffffu, best1, off);
        oi = __shfl_xor_sync(0xffffffffu, bi1,   off);
        if (ov > best1 || (ov == best1 && oi < bi1)) { best1 = ov; bi1 = oi; }
    }
    if (lane == 0) {
        g_assign[b*NP + row0]     = bi0;
        g_assign[b*NP + row0 + 1] = bi1;
    }
}

/* ------------ KNN (exact sorted top-64 via bitonic) + masked loss ------------ */
__global__ void __launch_bounds__(256) knn_loss_kernel(
    const float* __restrict__ inputs,
    const float* __restrict__ preds)
{
    __shared__ unsigned long long keys[NP];
    __shared__ float redm[KNN], redw[KNN];
    __shared__ float sh_d63;

    int row = blockIdx.x;
    int b = row >> 11, n = row & (NP - 1);
    const float* inp = inputs + b*NP*3;
    float ax = tf32r(inp[3*n]), ay = tf32r(inp[3*n+1]), az = tf32r(inp[3*n+2]);
    float sa = g_sin[b*NP + n];

    for (int m = threadIdx.x; m < NP; m += 256) {
        float bx = tf32r(inp[3*m]), by = tf32r(inp[3*m+1]), bz = tf32r(inp[3*m+2]);
        float dot = fmaf(az, bz, fmaf(ay, by, ax * bx));
        float d2  = fmaxf(__fadd_rn(__fadd_rn(sa, g_sin[b*NP + m]), -2.0f * dot), 0.f);
        keys[m] = (((unsigned long long)__float_as_uint(d2)) << 32) | (unsigned)m;
    }
    __syncthreads();

    /* ascending bitonic sort: key = (d2_bits, idx) reproduces top_k stable ties */
    for (int k = 2; k <= NP; k <<= 1) {
        for (int j = k >> 1; j > 0; j >>= 1) {
            for (int i = threadIdx.x; i < NP; i += 256) {
                int ixj = i ^ j;
                if (ixj > i) {
                    unsigned long long x = keys[i], y = keys[ixj];
                    bool up = ((i & k) == 0);
                    if ((x > y) == up) { keys[i] = y; keys[ixj] = x; }
                }
            }
            __syncthreads();
        }
    }

    int tid = threadIdx.x;
    if (tid < KNN) {
        unsigned long long key = keys[tid + 1];   /* drop self (rank 0) */
        int   idx = (int)(key & 0xffffffffull);
        float d   = __uint_as_float((unsigned)(key >> 32));

        const float C1 = (float)(0.05 * 0.05);
        const float C2 = (float)(2.0 * 0.5657 * 0.5657);
        const float C3 = (float)(0.5657 * 2.5066282746);
        float prob = expf(-(d / C1) / C2) / C3;

        /* exact JAX uniform(key(42), (4,2048,64)) */
        unsigned lin = ((unsigned)row << 6) | (unsigned)tid;
        const unsigned H = (unsigned)(BB * NP * KNN / 2);   /* 262144 */
        unsigned x0, x1, bits;
        if (lin < H) { x0 = lin;     x1 = lin + H; threefry2x32(0u, 42u, x0, x1); bits = x0; }
        else         { x0 = lin - H; x1 = lin;     threefry2x32(0u, 42u, x0, x1); bits = x1; }
        float u = __uint_as_float((bits >> 9) | 0x3f800000u) - 1.0f;
        float mask = (u < prob) ? 1.0f : 0.0f;

        int pidx = g_assign[b*NP + n];
        const float* pp = preds + (b*NP + pidx)*3;
        const float* xp = inp + idx*3;
        float dx = pp[0] - xp[0], dy = pp[1] - xp[1], dz = pp[2] - xp[2];
        float dist = fmaf(dz, dz, fmaf(dy, dy, dx * dx));

        redm[tid] = mask;
        redw[tid] = mask * dist;
        if (tid == KNN - 1) sh_d63 = dist;
    }
    __syncthreads();

    if (tid == 0) {
        float ms = 0.f, ws = 0.f;
#pragma unroll
        for (int q = 0; q < KNN; q++) { ms += redm[q]; ws += redw[q]; }
        g_avg[row] = (ms == 0.f) ? sh_d63 : (ws / ms);
    }
}

/* ------------ deterministic final reduction ------------ */
__global__ void reduce_kernel(float* __restrict__ out)
{
    __shared__ float sh[256];
    float s = 0.f;
    for (int i = threadIdx.x; i < BB*NP; i += 256) s += g_avg[i];
    sh[threadIdx.x] = s;
    __syncthreads();
    for (int off = 128; off; off >>= 1) {
        if (threadIdx.x < off) sh[threadIdx.x] += sh[threadIdx.x + off];
        __syncthreads();
    }
    if (threadIdx.x == 0) out[0] = sh[0];
}

extern "C" void kernel_launch(void* const* d_in, const int* in_sizes, int n_in,
                              void* d_out, int out_size)
{
    const float* preds  = (const float*)d_in[0];
    const float* inputs = (const float*)d_in[1];

    init_kernel<<<(BB*NP + 255) / 256, 256>>>(preds, inputs);

    dim3 g(NP / 16, BB);
    for (int it = 0; it < 50; ++it) {
        sinkhorn_half<0><<<g, 256>>>(inputs, preds);   /* lu <- f(lv) */
        sinkhorn_half<1><<<g, 256>>>(preds, inputs);   /* lv <- f(lu) */
    }
    assign_kernel<<<g, 256>>>(inputs, preds);
    knn_loss_kernel<<<BB*NP, 256>>>(inputs, preds);
    reduce_kernel<<<1, 256>>>((float*)d_out);
}

// round 4
// speedup vs baseline: 1.3893x; 1.3893x over previous
#include <cuda_runtime.h>
#include <math_constants.h>

#define BB   4
#define NP   2048
#define KNN  64
#define EPS  0.005f
#define LOG_MU (-7.6246190f)   /* -log(2048) */

/* ------------ scratch (no allocations allowed) ------------ */
__device__ float g_lu[BB*NP];
__device__ float g_lv[BB*NP];
__device__ float g_sin[BB*NP];
__device__ float g_spr[BB*NP];
__device__ int   g_assign[BB*NP];
__device__ float g_avg[BB*NP];
/* materialized logK = -C/eps : [b][n][m], and bit-exact transpose [b][m][n] */
__device__ float g_K [(size_t)BB*NP*NP];
__device__ float g_KT[(size_t)BB*NP*NP];

/* TF32 rounding (cuBLAS/CUTLASS conversion path: round-nearest-ties-away) */
__device__ __forceinline__ float tf32r(float x)
{
    float r;
    asm("cvt.rna.tf32.f32 %0, %1;" : "=f"(r) : "f"(x));
    return r;
}

/* ------------ threefry2x32, bit-exact vs JAX ------------ */
__device__ __forceinline__ void threefry2x32(unsigned k0, unsigned k1,
                                             unsigned &x0, unsigned &x1)
{
    unsigned ks2 = k0 ^ k1 ^ 0x1BD11BDAu;
    x0 += k0; x1 += k1;
#define TFR(r) { x0 += x1; x1 = (x1 << (r)) | (x1 >> (32 - (r))); x1 ^= x0; }
    TFR(13) TFR(15) TFR(26) TFR(6)
    x0 += k1;  x1 += ks2 + 1u;
    TFR(17) TFR(29) TFR(16) TFR(24)
    x0 += ks2; x1 += k0 + 2u;
    TFR(13) TFR(15) TFR(26) TFR(6)
    x0 += k0;  x1 += k1 + 3u;
    TFR(17) TFR(29) TFR(16) TFR(24)
    x0 += k1;  x1 += ks2 + 4u;
    TFR(13) TFR(15) TFR(26) TFR(6)
    x0 += ks2; x1 += k0 + 5u;
#undef TFR
}

/* ------------ init: squared norms (full fp32) + zero duals ------------ */
__global__ void init_kernel(const float* __restrict__ preds,
                            const float* __restrict__ inputs)
{
    int i = blockIdx.x * blockDim.x + threadIdx.x;
    if (i < BB*NP) {
        float x = inputs[3*i], y = inputs[3*i+1], z = inputs[3*i+2];
        g_sin[i] = fmaf(z, z, fmaf(y, y, x*x));
        x = preds[3*i]; y = preds[3*i+1]; z = preds[3*i+2];
        g_spr[i] = fmaf(z, z, fmaf(y, y, x*x));
        g_lu[i] = 0.f;
        g_lv[i] = 0.f;
    }
}

/* ------------ build logK (DIR=0: rows=inputs -> g_K[n][m])
                    or logKT (DIR=1: rows=preds -> g_KT[m][n]).
   Entry formula identical in both (fp32 add & mul commutative, fma chain
   structure unchanged) so g_KT[m][n] is bit-equal to g_K[n][m].          */
template<int DIR>
__global__ void __launch_bounds__(256) build_logK(
    const float* __restrict__ rowPts,
    const float* __restrict__ innerPts)
{
    __shared__ float4 shp[NP];
    const float* rowS   = (DIR == 0) ? g_sin : g_spr;
    const float* innerS = (DIR == 0) ? g_spr : g_sin;
    float*       out    = (DIR == 0) ? g_K   : g_KT;

    int b = blockIdx.y;
    const float* ip = innerPts + b*NP*3;
    for (int i = threadIdx.x; i < NP; i += 256)
        shp[i] = make_float4(tf32r(ip[3*i]), tf32r(ip[3*i+1]), tf32r(ip[3*i+2]),
                             innerS[b*NP + i]);
    __syncthreads();

    int warp = threadIdx.x >> 5, lane = threadIdx.x & 31;
    int row = blockIdx.x * 8 + warp;
    const float* rp = rowPts + (b*NP + row)*3;
    float ax = tf32r(rp[0]), ay = tf32r(rp[1]), az = tf32r(rp[2]);
    float sa = rowS[b*NP + row];
    float* orow = out + ((size_t)b*NP + row) * NP;

    for (int m = lane; m < NP; m += 32) {
        float4 p = shp[m];
        float dot = fmaf(az, p.z, fmaf(ay, p.y, ax * p.x));
        float d2  = fmaxf(__fadd_rn(__fadd_rn(sa, p.w), -2.0f * dot), 0.f);
        orow[m] = -(d2 / EPS);
    }
}

/* ------------ one Sinkhorn half-step over a materialized matrix ------------
   MAT==0: mat=g_K,  dualIn=g_lv, dualOut=g_lu
   MAT==1: mat=g_KT, dualIn=g_lu, dualOut=g_lv
   All __device__ symbols referenced from DEVICE code (host-side symbol
   addresses are the host shadows — the round-3 bug).                      */
template<int MAT>
__global__ void __launch_bounds__(256) sinkhorn_fast(void)
{
    const float* mat     = (MAT == 0) ? g_K  : g_KT;
    const float* dualIn  = (MAT == 0) ? g_lv : g_lu;
    float*       dualOut = (MAT == 0) ? g_lu : g_lv;

    __shared__ float shl[NP];
    int b = blockIdx.y;
    for (int i = threadIdx.x; i < NP; i += 256) shl[i] = dualIn[b*NP + i];
    __syncthreads();

    int warp = threadIdx.x >> 5, lane = threadIdx.x & 31;
    int row = blockIdx.x * 8 + warp;
    const float4* M4 = (const float4*)(mat + ((size_t)b*NP + row) * NP);
    const float4* L4 = (const float4*)shl;

    float mx0 = -CUDART_INF_F, mx1 = -CUDART_INF_F,
          mx2 = -CUDART_INF_F, mx3 = -CUDART_INF_F;
    float s0 = 0.f, s1 = 0.f, s2 = 0.f, s3 = 0.f;

#define ONLSE(e, mx, s) \
    { if ((e) > (mx)) { (s) = fmaf((s), expf((mx) - (e)), 1.f); (mx) = (e); } \
      else              (s) += expf((e) - (mx)); }

#pragma unroll 4
    for (int i = 0; i < NP/128; i++) {
        float4 k = M4[i*32 + lane];
        float4 l = L4[i*32 + lane];
        float e;
        e = __fadd_rn(k.x, l.x); ONLSE(e, mx0, s0)
        e = __fadd_rn(k.y, l.y); ONLSE(e, mx1, s1)
        e = __fadd_rn(k.z, l.z); ONLSE(e, mx2, s2)
        e = __fadd_rn(k.w, l.w); ONLSE(e, mx3, s3)
    }
#undef ONLSE

    /* merge the 4 accumulators */
    float nm, s, mx;
    nm = fmaxf(mx0, mx1); s0 = s0 * expf(mx0 - nm) + s1 * expf(mx1 - nm); mx0 = nm;
    nm = fmaxf(mx2, mx3); s2 = s2 * expf(mx2 - nm) + s3 * expf(mx3 - nm); mx2 = nm;
    nm = fmaxf(mx0, mx2); s  = s0 * expf(mx0 - nm) + s2 * expf(mx2 - nm); mx = nm;

#pragma unroll
    for (int off = 16; off; off >>= 1) {
        float om = __shfl_xor_sync(0xffffffffu, mx, off);
        float os = __shfl_xor_sync(0xffffffffu, s,  off);
        nm = fmaxf(mx, om);
        s  = s * expf(mx - nm) + os * expf(om - nm);
        mx = nm;
    }
    if (lane == 0) {
        float r = __fadd_rn(logf(s), mx);
        dualOut[b*NP + row] = __fadd_rn(LOG_MU, -r);
    }
}

/* ------------ argmax over m of g_K[n][m] + lv[m]  (lu[n] const per row) ------------ */
__global__ void __launch_bounds__(256) assign_fast(void)
{
    __shared__ float shl[NP];
    int b = blockIdx.y;
    for (int i = threadIdx.x; i < NP; i += 256) shl[i] = g_lv[b*NP + i];
    __syncthreads();

    int warp = threadIdx.x >> 5, lane = threadIdx.x & 31;
    int row = blockIdx.x * 8 + warp;
    const float4* M4 = (const float4*)(g_K + ((size_t)b*NP + row) * NP);
    const float4* L4 = (const float4*)shl;

    float best = -CUDART_INF_F;
    int   bi = 0;
    for (int i = 0; i < NP/128; i++) {
        float4 k = M4[i*32 + lane];
        float4 l = L4[i*32 + lane];
        int m0 = (i*32 + lane) * 4;
        float v;
        v = __fadd_rn(k.x, l.x); if (v > best) { best = v; bi = m0;     }
        v = __fadd_rn(k.y, l.y); if (v > best) { best = v; bi = m0 + 1; }
        v = __fadd_rn(k.z, l.z); if (v > best) { best = v; bi = m0 + 2; }
        v = __fadd_rn(k.w, l.w); if (v > best) { best = v; bi = m0 + 3; }
    }
#pragma unroll
    for (int off = 16; off; off >>= 1) {
        float ov = __shfl_xor_sync(0xffffffffu, best, off);
        int   oi = __shfl_xor_sync(0xffffffffu, bi,   off);
        if (ov > best || (ov == best && oi < bi)) { best = ov; bi = oi; }
    }
    if (lane == 0) g_assign[b*NP + row] = bi;
}

/* ------------ KNN (exact sorted top-64 via bitonic) + masked loss ------------ */
__global__ void __launch_bounds__(256) knn_loss_kernel(
    const float* __restrict__ inputs,
    const float* __restrict__ preds)
{
    __shared__ unsigned long long keys[NP];
    __shared__ float redm[KNN], redw[KNN];
    __shared__ float sh_d63;

    int row = blockIdx.x;
    int b = row >> 11, n = row & (NP - 1);
    const float* inp = inputs + b*NP*3;
    float ax = tf32r(inp[3*n]), ay = tf32r(inp[3*n+1]), az = tf32r(inp[3*n+2]);
    float sa = g_sin[b*NP + n];

    for (int m = threadIdx.x; m < NP; m += 256) {
        float bx = tf32r(inp[3*m]), by = tf32r(inp[3*m+1]), bz = tf32r(inp[3*m+2]);
        float dot = fmaf(az, bz, fmaf(ay, by, ax * bx));
        float d2  = fmaxf(__fadd_rn(__fadd_rn(sa, g_sin[b*NP + m]), -2.0f * dot), 0.f);
        keys[m] = (((unsigned long long)__float_as_uint(d2)) << 32) | (unsigned)m;
    }
    __syncthreads();

    /* ascending bitonic sort: key = (d2_bits, idx) reproduces top_k stable ties */
    for (int k = 2; k <= NP; k <<= 1) {
        for (int j = k >> 1; j > 0; j >>= 1) {
            for (int i = threadIdx.x; i < NP; i += 256) {
                int ixj = i ^ j;
                if (ixj > i) {
                    unsigned long long x = keys[i], y = keys[ixj];
                    bool up = ((i & k) == 0);
                    if ((x > y) == up) { keys[i] = y; keys[ixj] = x; }
                }
            }
            __syncthreads();
        }
    }

    int tid = threadIdx.x;
    if (tid < KNN) {
        unsigned long long key = keys[tid + 1];   /* drop self (rank 0) */
        int   idx = (int)(key & 0xffffffffull);
        float d   = __uint_as_float((unsigned)(key >> 32));

        const float C1 = (float)(0.05 * 0.05);
        const float C2 = (float)(2.0 * 0.5657 * 0.5657);
        const float C3 = (float)(0.5657 * 2.5066282746);
        float prob = expf(-(d / C1) / C2) / C3;

        /* exact JAX uniform(key(42), (4,2048,64)) */
        unsigned lin = ((unsigned)row << 6) | (unsigned)tid;
        const unsigned H = (unsigned)(BB * NP * KNN / 2);   /* 262144 */
        unsigned x0, x1, bits;
        if (lin < H) { x0 = lin;     x1 = lin + H; threefry2x32(0u, 42u, x0, x1); bits = x0; }
        else         { x0 = lin - H; x1 = lin;     threefry2x32(0u, 42u, x0, x1); bits = x1; }
        float u = __uint_as_float((bits >> 9) | 0x3f800000u) - 1.0f;
        float mask = (u < prob) ? 1.0f : 0.0f;

        int pidx = g_assign[b*NP + n];
        const float* pp = preds + (b*NP + pidx)*3;
        const float* xp = inp + idx*3;
        float dx = pp[0] - xp[0], dy = pp[1] - xp[1], dz = pp[2] - xp[2];
        float dist = fmaf(dz, dz, fmaf(dy, dy, dx * dx));

        redm[tid] = mask;
        redw[tid] = mask * dist;
        if (tid == KNN - 1) sh_d63 = dist;
    }
    __syncthreads();

    if (tid == 0) {
        float ms = 0.f, ws = 0.f;
#pragma unroll
        for (int q = 0; q < KNN; q++) { ms += redm[q]; ws += redw[q]; }
        g_avg[row] = (ms == 0.f) ? sh_d63 : (ws / ms);
    }
}

/* ------------ deterministic final reduction ------------ */
__global__ void reduce_kernel(float* __restrict__ out)
{
    __shared__ float sh[256];
    float s = 0.f;
    for (int i = threadIdx.x; i < BB*NP; i += 256) s += g_avg[i];
    sh[threadIdx.x] = s;
    __syncthreads();
    for (int off = 128; off; off >>= 1) {
        if (threadIdx.x < off) sh[threadIdx.x] += sh[threadIdx.x + off];
        __syncthreads();
    }
    if (threadIdx.x == 0) out[0] = sh[0];
}

extern "C" void kernel_launch(void* const* d_in, const int* in_sizes, int n_in,
                              void* d_out, int out_size)
{
    const float* preds  = (const float*)d_in[0];
    const float* inputs = (const float*)d_in[1];

    init_kernel<<<(BB*NP + 255) / 256, 256>>>(preds, inputs);

    dim3 g(NP / 8, BB);
    build_logK<0><<<g, 256>>>(inputs, preds);   /* g_K [n][m] */
    build_logK<1><<<g, 256>>>(preds, inputs);   /* g_KT[m][n] */

    for (int it = 0; it < 50; ++it) {
        sinkhorn_fast<0><<<g, 256>>>();   /* lu <- f(g_K,  lv) */
        sinkhorn_fast<1><<<g, 256>>>();   /* lv <- f(g_KT, lu) */
    }
    assign_fast<<<g, 256>>>();
    knn_loss_kernel<<<BB*NP, 256>>>(inputs, preds);
    reduce_kernel<<<1, 256>>>((float*)d_out);
}

// round 5
// speedup vs baseline: 1.5415x; 1.1096x over previous
#include <cuda_runtime.h>
#include <math_constants.h>

#define BB   4
#define NP   2048
#define KNN  64
#define EPS  0.005f
#define LOG_MU (-7.6246190f)   /* -log(2048) */

/* ------------ scratch (no allocations allowed) ------------ */
__device__ float g_lu[BB*NP];
__device__ float g_lv[BB*NP];
__device__ float g_sin[BB*NP];
__device__ float g_spr[BB*NP];
__device__ int   g_assign[BB*NP];
__device__ float g_avg[BB*NP];
/* materialized logK = -C/eps : [b][n][m], and bit-exact transpose [b][m][n] */
__device__ float g_K [(size_t)BB*NP*NP];
__device__ float g_KT[(size_t)BB*NP*NP];

/* TF32 rounding (cuBLAS/CUTLASS conversion path: round-nearest-ties-away) */
__device__ __forceinline__ float tf32r(float x)
{
    float r;
    asm("cvt.rna.tf32.f32 %0, %1;" : "=f"(r) : "f"(x));
    return r;
}

/* ------------ threefry2x32, bit-exact vs JAX ------------ */
__device__ __forceinline__ void threefry2x32(unsigned k0, unsigned k1,
                                             unsigned &x0, unsigned &x1)
{
    unsigned ks2 = k0 ^ k1 ^ 0x1BD11BDAu;
    x0 += k0; x1 += k1;
#define TFR(r) { x0 += x1; x1 = (x1 << (r)) | (x1 >> (32 - (r))); x1 ^= x0; }
    TFR(13) TFR(15) TFR(26) TFR(6)
    x0 += k1;  x1 += ks2 + 1u;
    TFR(17) TFR(29) TFR(16) TFR(24)
    x0 += ks2; x1 += k0 + 2u;
    TFR(13) TFR(15) TFR(26) TFR(6)
    x0 += k0;  x1 += k1 + 3u;
    TFR(17) TFR(29) TFR(16) TFR(24)
    x0 += k1;  x1 += ks2 + 4u;
    TFR(13) TFR(15) TFR(26) TFR(6)
    x0 += ks2; x1 += k0 + 5u;
#undef TFR
}

/* ------------ init: squared norms (full fp32) + zero duals ------------ */
__global__ void init_kernel(const float* __restrict__ preds,
                            const float* __restrict__ inputs)
{
    int i = blockIdx.x * blockDim.x + threadIdx.x;
    if (i < BB*NP) {
        float x = inputs[3*i], y = inputs[3*i+1], z = inputs[3*i+2];
        g_sin[i] = fmaf(z, z, fmaf(y, y, x*x));
        x = preds[3*i]; y = preds[3*i+1]; z = preds[3*i+2];
        g_spr[i] = fmaf(z, z, fmaf(y, y, x*x));
        g_lu[i] = 0.f;
        g_lv[i] = 0.f;
    }
}

/* ------------ build logK (DIR=0: rows=inputs -> g_K[n][m])
                    or logKT (DIR=1: rows=preds -> g_KT[m][n]).
   Entry formula identical in both (fp32 add & mul commutative, fma chain
   structure unchanged) so g_KT[m][n] is bit-equal to g_K[n][m].          */
template<int DIR>
__global__ void __launch_bounds__(256) build_logK(
    const float* __restrict__ rowPts,
    const float* __restrict__ innerPts)
{
    __shared__ float4 shp[NP];
    const float* rowS   = (DIR == 0) ? g_sin : g_spr;
    const float* innerS = (DIR == 0) ? g_spr : g_sin;
    float*       out    = (DIR == 0) ? g_K   : g_KT;

    int b = blockIdx.y;
    const float* ip = innerPts + b*NP*3;
    for (int i = threadIdx.x; i < NP; i += 256)
        shp[i] = make_float4(tf32r(ip[3*i]), tf32r(ip[3*i+1]), tf32r(ip[3*i+2]),
                             innerS[b*NP + i]);
    __syncthreads();

    int warp = threadIdx.x >> 5, lane = threadIdx.x & 31;
    int row = blockIdx.x * 8 + warp;
    const float* rp = rowPts + (b*NP + row)*3;
    float ax = tf32r(rp[0]), ay = tf32r(rp[1]), az = tf32r(rp[2]);
    float sa = rowS[b*NP + row];
    float* orow = out + ((size_t)b*NP + row) * NP;

    for (int m = lane; m < NP; m += 32) {
        float4 p = shp[m];
        float dot = fmaf(az, p.z, fmaf(ay, p.y, ax * p.x));
        float d2  = fmaxf(__fadd_rn(__fadd_rn(sa, p.w), -2.0f * dot), 0.f);
        orow[m] = -(d2 / EPS);
    }
}

/* ------------ one Sinkhorn half-step over a materialized matrix ------------
   MAT==0: mat=g_K,  dualIn=g_lv, dualOut=g_lu
   MAT==1: mat=g_KT, dualIn=g_lu, dualOut=g_lv
   Register-resident two-pass logsumexp:
     pass1: e = k + dual (kept in 64 regs), row max via fmaxf + shfl
     pass2: s += __expf(e - mx) with fixed shift -> plain-add reduction.  */
template<int MAT>
__global__ void __launch_bounds__(256) sinkhorn_fast(void)
{
    const float* mat     = (MAT == 0) ? g_K  : g_KT;
    const float* dualIn  = (MAT == 0) ? g_lv : g_lu;
    float*       dualOut = (MAT == 0) ? g_lu : g_lv;

    __shared__ float shl[NP];
    int b = blockIdx.y;
    for (int i = threadIdx.x; i < NP; i += 256) shl[i] = dualIn[b*NP + i];
    __syncthreads();

    int warp = threadIdx.x >> 5, lane = threadIdx.x & 31;
    int row = blockIdx.x * 8 + warp;
    const float4* M4 = (const float4*)(mat + ((size_t)b*NP + row) * NP);
    const float4* L4 = (const float4*)shl;

    float4 e[16];
    float mx = -CUDART_INF_F;
#pragma unroll
    for (int i = 0; i < 16; i++) {
        float4 k = M4[i*32 + lane];
        float4 l = L4[i*32 + lane];
        e[i].x = __fadd_rn(k.x, l.x);
        e[i].y = __fadd_rn(k.y, l.y);
        e[i].z = __fadd_rn(k.z, l.z);
        e[i].w = __fadd_rn(k.w, l.w);
        mx = fmaxf(mx, fmaxf(fmaxf(e[i].x, e[i].y), fmaxf(e[i].z, e[i].w)));
    }
#pragma unroll
    for (int off = 16; off; off >>= 1)
        mx = fmaxf(mx, __shfl_xor_sync(0xffffffffu, mx, off));

    float s0 = 0.f, s1 = 0.f, s2 = 0.f, s3 = 0.f;
#pragma unroll
    for (int i = 0; i < 16; i++) {
        s0 += __expf(__fadd_rn(e[i].x, -mx));
        s1 += __expf(__fadd_rn(e[i].y, -mx));
        s2 += __expf(__fadd_rn(e[i].z, -mx));
        s3 += __expf(__fadd_rn(e[i].w, -mx));
    }
    float s = (s0 + s1) + (s2 + s3);
#pragma unroll
    for (int off = 16; off; off >>= 1)
        s += __shfl_xor_sync(0xffffffffu, s, off);

    if (lane == 0) {
        float r = __fadd_rn(logf(s), mx);
        dualOut[b*NP + row] = __fadd_rn(LOG_MU, -r);
    }
}

/* ------------ argmax over m of g_K[n][m] + lv[m]  (lu[n] const per row) ------------ */
__global__ void __launch_bounds__(256) assign_fast(void)
{
    __shared__ float shl[NP];
    int b = blockIdx.y;
    for (int i = threadIdx.x; i < NP; i += 256) shl[i] = g_lv[b*NP + i];
    __syncthreads();

    int warp = threadIdx.x >> 5, lane = threadIdx.x & 31;
    int row = blockIdx.x * 8 + warp;
    const float4* M4 = (const float4*)(g_K + ((size_t)b*NP + row) * NP);
    const float4* L4 = (const float4*)shl;

    float best = -CUDART_INF_F;
    int   bi = 0;
    for (int i = 0; i < NP/128; i++) {
        float4 k = M4[i*32 + lane];
        float4 l = L4[i*32 + lane];
        int m0 = (i*32 + lane) * 4;
        float v;
        v = __fadd_rn(k.x, l.x); if (v > best) { best = v; bi = m0;     }
        v = __fadd_rn(k.y, l.y); if (v > best) { best = v; bi = m0 + 1; }
        v = __fadd_rn(k.z, l.z); if (v > best) { best = v; bi = m0 + 2; }
        v = __fadd_rn(k.w, l.w); if (v > best) { best = v; bi = m0 + 3; }
    }
#pragma unroll
    for (int off = 16; off; off >>= 1) {
        float ov = __shfl_xor_sync(0xffffffffu, best, off);
        int   oi = __shfl_xor_sync(0xffffffffu, bi,   off);
        if (ov > best || (ov == best && oi < bi)) { best = ov; bi = oi; }
    }
    if (lane == 0) g_assign[b*NP + row] = bi;
}

/* ------------ KNN (exact sorted top-64 via bitonic) + masked loss ------------ */
__global__ void __launch_bounds__(256) knn_loss_kernel(
    const float* __restrict__ inputs,
    const float* __restrict__ preds)
{
    __shared__ unsigned long long keys[NP];
    __shared__ float redm[KNN], redw[KNN];
    __shared__ float sh_d63;

    int row = blockIdx.x;
    int b = row >> 11, n = row & (NP - 1);
    const float* inp = inputs + b*NP*3;
    float ax = tf32r(inp[3*n]), ay = tf32r(inp[3*n+1]), az = tf32r(inp[3*n+2]);
    float sa = g_sin[b*NP + n];

    for (int m = threadIdx.x; m < NP; m += 256) {
        float bx = tf32r(inp[3*m]), by = tf32r(inp[3*m+1]), bz = tf32r(inp[3*m+2]);
        float dot = fmaf(az, bz, fmaf(ay, by, ax * bx));
        float d2  = fmaxf(__fadd_rn(__fadd_rn(sa, g_sin[b*NP + m]), -2.0f * dot), 0.f);
        keys[m] = (((unsigned long long)__float_as_uint(d2)) << 32) | (unsigned)m;
    }
    __syncthreads();

    /* ascending bitonic sort: key = (d2_bits, idx) reproduces top_k stable ties */
    for (int k = 2; k <= NP; k <<= 1) {
        for (int j = k >> 1; j > 0; j >>= 1) {
            for (int i = threadIdx.x; i < NP; i += 256) {
                int ixj = i ^ j;
                if (ixj > i) {
                    unsigned long long x = keys[i], y = keys[ixj];
                    bool up = ((i & k) == 0);
                    if ((x > y) == up) { keys[i] = y; keys[ixj] = x; }
                }
            }
            __syncthreads();
        }
    }

    int tid = threadIdx.x;
    if (tid < KNN) {
        unsigned long long key = keys[tid + 1];   /* drop self (rank 0) */
        int   idx = (int)(key & 0xffffffffull);
        float d   = __uint_as_float((unsigned)(key >> 32));

        const float C1 = (float)(0.05 * 0.05);
        const float C2 = (float)(2.0 * 0.5657 * 0.5657);
        const float C3 = (float)(0.5657 * 2.5066282746);
        float prob = expf(-(d / C1) / C2) / C3;

        /* exact JAX uniform(key(42), (4,2048,64)) */
        unsigned lin = ((unsigned)row << 6) | (unsigned)tid;
        const unsigned H = (unsigned)(BB * NP * KNN / 2);   /* 262144 */
        unsigned x0, x1, bits;
        if (lin < H) { x0 = lin;     x1 = lin + H; threefry2x32(0u, 42u, x0, x1); bits = x0; }
        else         { x0 = lin - H; x1 = lin;     threefry2x32(0u, 42u, x0, x1); bits = x1; }
        float u = __uint_as_float((bits >> 9) | 0x3f800000u) - 1.0f;
        float mask = (u < prob) ? 1.0f : 0.0f;

        int pidx = g_assign[b*NP + n];
        const float* pp = preds + (b*NP + pidx)*3;
        const float* xp = inp + idx*3;
        float dx = pp[0] - xp[0], dy = pp[1] - xp[1], dz = pp[2] - xp[2];
        float dist = fmaf(dz, dz, fmaf(dy, dy, dx * dx));

        redm[tid] = mask;
        redw[tid] = mask * dist;
        if (tid == KNN - 1) sh_d63 = dist;
    }
    __syncthreads();

    if (tid == 0) {
        float ms = 0.f, ws = 0.f;
#pragma unroll
        for (int q = 0; q < KNN; q++) { ms += redm[q]; ws += redw[q]; }
        g_avg[row] = (ms == 0.f) ? sh_d63 : (ws / ms);
    }
}

/* ------------ deterministic final reduction ------------ */
__global__ void reduce_kernel(float* __restrict__ out)
{
    __shared__ float sh[256];
    float s = 0.f;
    for (int i = threadIdx.x; i < BB*NP; i += 256) s += g_avg[i];
    sh[threadIdx.x] = s;
    __syncthreads();
    for (int off = 128; off; off >>= 1) {
        if (threadIdx.x < off) sh[threadIdx.x] += sh[threadIdx.x + off];
        __syncthreads();
    }
    if (threadIdx.x == 0) out[0] = sh[0];
}

extern "C" void kernel_launch(void* const* d_in, const int* in_sizes, int n_in,
                              void* d_out, int out_size)
{
    const float* preds  = (const float*)d_in[0];
    const float* inputs = (const float*)d_in[1];

    init_kernel<<<(BB*NP + 255) / 256, 256>>>(preds, inputs);

    dim3 g(NP / 8, BB);
    build_logK<0><<<g, 256>>>(inputs, preds);   /* g_K [n][m] */
    build_logK<1><<<g, 256>>>(preds, inputs);   /* g_KT[m][n] */

    for (int it = 0; it < 50; ++it) {
        sinkhorn_fast<0><<<g, 256>>>();   /* lu <- f(g_K,  lv) */
        sinkhorn_fast<1><<<g, 256>>>();   /* lv <- f(g_KT, lu) */
    }
    assign_fast<<<g, 256>>>();
    knn_loss_kernel<<<BB*NP, 256>>>(inputs, preds);
    reduce_kernel<<<1, 256>>>((float*)d_out);
}